// round 4
// baseline (speedup 1.0000x reference)
#include <cuda_runtime.h>
#include <math.h>

// GeodesicLoss: reference initializes velocity to zero, so the geodesic ODE
// acc = -Gamma v v is identically zero for all 10 steps -> traj == outputs.
// Result is exactly mean_b || outputs_b - targets_b ||_2.
// Pure streaming reduction over 128 MiB -> DRAM-bound.
//
// R4: replicate R1's fastest streaming layout (4M threads, one float4-pair
// per thread -> warp-count supplies the MLP), 1024-thread blocks so the
// fused last-block-done tail reduces only 4096 partials (one float4/thread).
// Fixed summation order -> deterministic; counter self-resets for replay.

#define B_ROWS   524288
#define D_DIM    32
#define THREADS  1024
#define NBLOCKS  4096        // NBLOCKS*THREADS = 4M threads = B_ROWS*8

__device__ float        g_partials[NBLOCKS];
__device__ unsigned int g_done_count = 0;

__global__ __launch_bounds__(THREADS)
void geodesic_loss_fused_kernel(const float* __restrict__ outputs,
                                const float* __restrict__ targets,
                                float* __restrict__ out) {
    const int tid = blockIdx.x * THREADS + threadIdx.x;
    const int row = tid >> 3;              // 8 lanes per row
    const int sub = threadIdx.x & 7;       // which float4 of the row

    const float4* __restrict__ o4 = reinterpret_cast<const float4*>(outputs);
    const float4* __restrict__ t4 = reinterpret_cast<const float4*>(targets);

    const int idx = row * (D_DIM / 4) + sub;
    float4 a = o4[idx];
    float4 b = t4[idx];

    float dx = a.x - b.x;
    float dy = a.y - b.y;
    float dz = a.z - b.z;
    float dw = a.w - b.w;
    float s = dx * dx + dy * dy + dz * dz + dw * dw;

    // Reduce the 8 lanes covering this row (butterfly)
    s += __shfl_xor_sync(0xFFFFFFFFu, s, 1);
    s += __shfl_xor_sync(0xFFFFFFFFu, s, 2);
    s += __shfl_xor_sync(0xFFFFFFFFu, s, 4);

    // One representative lane per row contributes sqrt(row_sum)
    float v = (sub == 0) ? sqrtf(s) : 0.0f;

    // Sum the 4 row-norms held in this warp (lanes 0,8,16,24)
    v += __shfl_xor_sync(0xFFFFFFFFu, v, 8);
    v += __shfl_xor_sync(0xFFFFFFFFu, v, 16);

    __shared__ float wsum[THREADS / 32];   // 32 warp sums
    if ((threadIdx.x & 31) == 0)
        wsum[threadIdx.x >> 5] = v;
    __syncthreads();

    __shared__ bool s_is_last;
    if (threadIdx.x < 32) {
        float w = wsum[threadIdx.x];
        w += __shfl_xor_sync(0xFFFFFFFFu, w, 1);
        w += __shfl_xor_sync(0xFFFFFFFFu, w, 2);
        w += __shfl_xor_sync(0xFFFFFFFFu, w, 4);
        w += __shfl_xor_sync(0xFFFFFFFFu, w, 8);
        w += __shfl_xor_sync(0xFFFFFFFFu, w, 16);
        if (threadIdx.x == 0) {
            g_partials[blockIdx.x] = w;
            __threadfence();
            unsigned int prev = atomicAdd(&g_done_count, 1u);
            s_is_last = (prev == NBLOCKS - 1);
        }
    }
    __syncthreads();

    if (s_is_last) {
        // Final reduce over 4096 partials: exactly one float4 per thread,
        // fixed traversal order -> deterministic.
        const float4* __restrict__ p4 =
            reinterpret_cast<const float4*>(g_partials);
        float4 vv = p4[threadIdx.x];
        float s2 = (vv.x + vv.y) + (vv.z + vv.w);

        s2 += __shfl_xor_sync(0xFFFFFFFFu, s2, 1);
        s2 += __shfl_xor_sync(0xFFFFFFFFu, s2, 2);
        s2 += __shfl_xor_sync(0xFFFFFFFFu, s2, 4);
        s2 += __shfl_xor_sync(0xFFFFFFFFu, s2, 8);
        s2 += __shfl_xor_sync(0xFFFFFFFFu, s2, 16);

        __shared__ float fsum[THREADS / 32];
        if ((threadIdx.x & 31) == 0)
            fsum[threadIdx.x >> 5] = s2;
        __syncthreads();

        if (threadIdx.x < 32) {
            float t = fsum[threadIdx.x];
            t += __shfl_xor_sync(0xFFFFFFFFu, t, 1);
            t += __shfl_xor_sync(0xFFFFFFFFu, t, 2);
            t += __shfl_xor_sync(0xFFFFFFFFu, t, 4);
            t += __shfl_xor_sync(0xFFFFFFFFu, t, 8);
            t += __shfl_xor_sync(0xFFFFFFFFu, t, 16);
            if (threadIdx.x == 0) {
                out[0] = t * (1.0f / (float)B_ROWS);
                g_done_count = 0;   // reset for next graph replay
            }
        }
    }
}

extern "C" void kernel_launch(void* const* d_in, const int* in_sizes, int n_in,
                              void* d_out, int out_size) {
    const float* outputs = (const float*)d_in[0];
    const float* targets = (const float*)d_in[1];
    // d_in[2] (christoffel_symbols) is mathematically dead: vel starts at 0.
    float* out = (float*)d_out;

    geodesic_loss_fused_kernel<<<NBLOCKS, THREADS>>>(outputs, targets, out);
}

// round 5
// speedup vs baseline: 1.0576x; 1.0576x over previous
#include <cuda_runtime.h>
#include <math.h>

// GeodesicLoss: reference initializes velocity to zero, so the geodesic ODE
// acc = -Gamma v v is identically zero for all 10 steps -> traj == outputs.
// Result is exactly mean_b || outputs_b - targets_b ||_2.
// Pure streaming reduction over 128 MiB -> DRAM-bound.
//
// R5: exact R1 streaming layout (block=256, grid=16384, one float4-pair per
// thread -- measured 5.8 TB/s), with the final reduce fused via the
// last-block-done pattern (fixed order -> deterministic; counter self-resets
// for graph replay) instead of R1's separate 5.3us kernel.

#define B_ROWS   524288
#define D_DIM    32
#define THREADS  256
#define NBLOCKS  16384       // NBLOCKS*THREADS = 4M threads = B_ROWS*8

__device__ float        g_partials[NBLOCKS];
__device__ unsigned int g_done_count = 0;

__global__ __launch_bounds__(THREADS)
void geodesic_loss_fused_kernel(const float* __restrict__ outputs,
                                const float* __restrict__ targets,
                                float* __restrict__ out) {
    const int tid = blockIdx.x * THREADS + threadIdx.x;
    const int row = tid >> 3;              // 8 lanes per row
    const int sub = threadIdx.x & 7;       // which float4 of the row

    const float4* __restrict__ o4 = reinterpret_cast<const float4*>(outputs);
    const float4* __restrict__ t4 = reinterpret_cast<const float4*>(targets);

    const int idx = row * (D_DIM / 4) + sub;
    float4 a = o4[idx];
    float4 b = t4[idx];

    float dx = a.x - b.x;
    float dy = a.y - b.y;
    float dz = a.z - b.z;
    float dw = a.w - b.w;
    float s = dx * dx + dy * dy + dz * dz + dw * dw;

    // Reduce the 8 lanes covering this row (butterfly)
    s += __shfl_xor_sync(0xFFFFFFFFu, s, 1);
    s += __shfl_xor_sync(0xFFFFFFFFu, s, 2);
    s += __shfl_xor_sync(0xFFFFFFFFu, s, 4);

    // One representative lane per row contributes sqrt(row_sum)
    float v = (sub == 0) ? sqrtf(s) : 0.0f;

    // Sum the 4 row-norms held in this warp (lanes 0,8,16,24)
    v += __shfl_xor_sync(0xFFFFFFFFu, v, 8);
    v += __shfl_xor_sync(0xFFFFFFFFu, v, 16);

    __shared__ float wsum[THREADS / 32];   // 8 warp sums
    if ((threadIdx.x & 31) == 0)
        wsum[threadIdx.x >> 5] = v;
    __syncthreads();

    __shared__ bool s_is_last;
    if (threadIdx.x == 0) {
        float bsum = 0.0f;
        #pragma unroll
        for (int i = 0; i < THREADS / 32; i++)
            bsum += wsum[i];
        g_partials[blockIdx.x] = bsum;
        __threadfence();
        unsigned int prev = atomicAdd(&g_done_count, 1u);
        s_is_last = (prev == NBLOCKS - 1);
    }
    __syncthreads();

    if (s_is_last) {
        // Final reduce over 16384 partials (64 KB, L2-resident):
        // 256 threads x 16 float4 loads, fixed order -> deterministic.
        const float4* __restrict__ p4 =
            reinterpret_cast<const float4*>(g_partials);
        float s2 = 0.0f;
        #pragma unroll
        for (int i = threadIdx.x; i < NBLOCKS / 4; i += THREADS) {
            float4 vv = p4[i];
            s2 += (vv.x + vv.y) + (vv.z + vv.w);
        }

        s2 += __shfl_xor_sync(0xFFFFFFFFu, s2, 1);
        s2 += __shfl_xor_sync(0xFFFFFFFFu, s2, 2);
        s2 += __shfl_xor_sync(0xFFFFFFFFu, s2, 4);
        s2 += __shfl_xor_sync(0xFFFFFFFFu, s2, 8);
        s2 += __shfl_xor_sync(0xFFFFFFFFu, s2, 16);

        __shared__ float fsum[THREADS / 32];
        if ((threadIdx.x & 31) == 0)
            fsum[threadIdx.x >> 5] = s2;
        __syncthreads();

        if (threadIdx.x == 0) {
            float tot = 0.0f;
            #pragma unroll
            for (int i = 0; i < THREADS / 32; i++)
                tot += fsum[i];
            out[0] = tot * (1.0f / (float)B_ROWS);
            g_done_count = 0;   // reset for next graph replay
        }
    }
}

extern "C" void kernel_launch(void* const* d_in, const int* in_sizes, int n_in,
                              void* d_out, int out_size) {
    const float* outputs = (const float*)d_in[0];
    const float* targets = (const float*)d_in[1];
    // d_in[2] (christoffel_symbols) is mathematically dead: vel starts at 0.
    float* out = (float*)d_out;

    geodesic_loss_fused_kernel<<<NBLOCKS, THREADS>>>(outputs, targets, out);
}